// round 14
// baseline (speedup 1.0000x reference)
#include <cuda_runtime.h>
#include <cuda_fp16.h>
#include <stdint.h>
#include <math.h>

#define HW 4096
#define NB 2

__device__ float g_M [(size_t)NB * HW * HW];   // M[b][j][i]
__device__ float g_MT[(size_t)NB * HW * HW];   // M[b][i][j]
__device__ float g_inv[4][NB * HW];            // 0:src3 1:tgt3 2:src4 3:tgt4

// K-major planes: fp16 hi limb + int8 quantized (hi, lo) limbs.
#define N3 ((size_t)NB * HW * 1024)
#define N4 ((size_t)NB * HW * 2048)
__device__ __align__(256) __half  g_h3s[N3], g_h3t[N3];
__device__ __align__(256) __half  g_h4s[N4], g_h4t[N4];
__device__ __align__(256) int8_t  g_q3s[2][N3], g_q3t[2][N3];
__device__ __align__(256) int8_t  g_q4s[2][N4], g_q4t[2][N4];

// int8 limb scales: a8h = round(ah * 20), a8l = round((a-ah) * 63500)
#define SC_H   20.0f
#define SC_L   63500.0f
#define SC_INV (1.0f / (SC_H * SC_L))

// ---------------------------------------------------------------------------
// PTX helpers (base sm_80 features only -> legal at compute_103)
// ---------------------------------------------------------------------------
__device__ __forceinline__ uint32_t su32(const void* p) {
    uint32_t a;
    asm("{ .reg .u64 t; cvta.to.shared.u64 t, %1; cvt.u32.u64 %0, t; }" : "=r"(a) : "l"(p));
    return a;
}
__device__ __forceinline__ void ldmx4(uint32_t* r, uint32_t a) {
    asm volatile("ldmatrix.sync.aligned.m8n8.x4.shared.b16 {%0,%1,%2,%3}, [%4];"
                 : "=r"(r[0]), "=r"(r[1]), "=r"(r[2]), "=r"(r[3]) : "r"(a));
}
__device__ __forceinline__ void ldmx2(uint32_t* r, uint32_t a) {
    asm volatile("ldmatrix.sync.aligned.m8n8.x2.shared.b16 {%0,%1}, [%2];"
                 : "=r"(r[0]), "=r"(r[1]) : "r"(a));
}
__device__ __forceinline__ void mma16816(float* d, const uint32_t* a, const uint32_t* b) {
    asm volatile(
        "mma.sync.aligned.m16n8k16.row.col.f32.f16.f16.f32 "
        "{%0,%1,%2,%3}, {%4,%5,%6,%7}, {%8,%9}, {%0,%1,%2,%3};"
        : "+f"(d[0]), "+f"(d[1]), "+f"(d[2]), "+f"(d[3])
        : "r"(a[0]), "r"(a[1]), "r"(a[2]), "r"(a[3]), "r"(b[0]), "r"(b[1]));
}
__device__ __forceinline__ void imma16832(int* d, const uint32_t* a, const uint32_t* b) {
    asm volatile(
        "mma.sync.aligned.m16n8k32.row.col.s32.s8.s8.s32 "
        "{%0,%1,%2,%3}, {%4,%5,%6,%7}, {%8,%9}, {%0,%1,%2,%3};"
        : "+r"(d[0]), "+r"(d[1]), "+r"(d[2]), "+r"(d[3])
        : "r"(a[0]), "r"(a[1]), "r"(a[2]), "r"(a[3]), "r"(b[0]), "r"(b[1]));
}
__device__ __forceinline__ void cpasync16(uint32_t dst, const void* src) {
    asm volatile("cp.async.cg.shared.global [%0], [%1], 16;" :: "r"(dst), "l"(src));
}
__device__ __forceinline__ void cp_commit() { asm volatile("cp.async.commit_group;"); }
__device__ __forceinline__ void cp_wait1()  { asm volatile("cp.async.wait_group 1;"); }
__device__ __forceinline__ void cp_wait0()  { asm volatile("cp.async.wait_group 0;"); }

// ---------------------------------------------------------------------------
// Kernel 1: per-position inverse channel norms.
// ---------------------------------------------------------------------------
__global__ void norm_kernel(const float* __restrict__ s3, const float* __restrict__ t3,
                            const float* __restrict__ s4, const float* __restrict__ t4)
{
    int gid   = blockIdx.x * 256 + threadIdx.x;
    int which = blockIdx.y;
    const float* x; int C;
    if      (which == 0) { x = s3; C = 1024; }
    else if (which == 1) { x = t3; C = 1024; }
    else if (which == 2) { x = s4; C = 2048; }
    else                 { x = t4; C = 2048; }

    int b = gid >> 12, pos = gid & (HW - 1);
    const float* p = x + (size_t)b * C * HW + pos;
    float ss0 = 0.f, ss1 = 0.f, ss2 = 0.f, ss3 = 0.f;
    for (int c = 0; c < C; c += 4) {
        float a0 = p[(size_t)(c + 0) * HW];
        float a1 = p[(size_t)(c + 1) * HW];
        float a2 = p[(size_t)(c + 2) * HW];
        float a3 = p[(size_t)(c + 3) * HW];
        ss0 = fmaf(a0, a0, ss0); ss1 = fmaf(a1, a1, ss1);
        ss2 = fmaf(a2, a2, ss2); ss3 = fmaf(a3, a3, ss3);
    }
    g_inv[which][gid] = rsqrtf((ss0 + ss1) + (ss2 + ss3) + 1e-6f);
}

// ---------------------------------------------------------------------------
// Kernel 1b: split + transpose prepass.
// [b][C][HW] fp32 -> fp16 hi plane + int8 (hi,lo) limb planes, K-major.
// grid (HW/64, C/64, NB) x 256
// ---------------------------------------------------------------------------
__global__ void __launch_bounds__(256)
split_kernel(const float* __restrict__ in, int which, int C)
{
    __shared__ float tile[64][65];
    __half* hh; int8_t* q8h; int8_t* q8l;
    if      (which == 0) { hh = g_h3s; q8h = g_q3s[0]; q8l = g_q3s[1]; }
    else if (which == 1) { hh = g_h3t; q8h = g_q3t[0]; q8l = g_q3t[1]; }
    else if (which == 2) { hh = g_h4s; q8h = g_q4s[0]; q8l = g_q4s[1]; }
    else                 { hh = g_h4t; q8h = g_q4t[0]; q8l = g_q4t[1]; }

    const int p0 = blockIdx.x * 64, c0 = blockIdx.y * 64, b = blockIdx.z;
    const float* src = in + (size_t)b * C * HW;
    const int tid = threadIdx.x;

#pragma unroll
    for (int l = 0; l < 16; ++l) {
        int idx = tid + l * 256;
        int c = idx >> 6, p = idx & 63;
        tile[c][p] = src[(size_t)(c0 + c) * HW + p0 + p];
    }
    __syncthreads();

    const int cg = tid & 7;
#pragma unroll
    for (int pass = 0; pass < 2; ++pass) {
        const int p = (tid >> 3) + pass * 32;
        union { __half h[8]; uint4 u; } H;
        uint32_t qh0 = 0, qh1 = 0, ql0 = 0, ql1 = 0;
#pragma unroll
        for (int e = 0; e < 8; ++e) {
            float v = tile[cg * 8 + e][p];
            __half h = __float2half_rn(v);
            H.h[e] = h;
            float hf = __half2float(h);
            int qh = __float2int_rn(fminf(fmaxf(hf * SC_H, -127.f), 127.f));
            int ql = __float2int_rn(fminf(fmaxf((v - hf) * SC_L, -127.f), 127.f));
            uint32_t bh = (uint32_t)qh & 255u, bl = (uint32_t)ql & 255u;
            if (e < 4) { qh0 |= bh << (8 * e);       ql0 |= bl << (8 * e); }
            else       { qh1 |= bh << (8 * (e - 4)); ql1 |= bl << (8 * (e - 4)); }
        }
        size_t o = ((size_t)b * HW + p0 + p) * C + c0 + cg * 8;
        *reinterpret_cast<uint4*>(hh + o)  = H.u;
        *reinterpret_cast<uint2*>(q8h + o) = make_uint2(qh0, qh1);
        *reinterpret_cast<uint2*>(q8l + o) = make_uint2(ql0, ql1);
    }
}

// ---------------------------------------------------------------------------
// Kernel 2: hybrid GEMM.  Main term ah*bh via HMMA f32; the two ~2^-11
// correction terms (ah*bl + al*bh) via one shared-accumulator IMMA pair
// (k32, int8 limbs) -> 4 MMA slots per (mi,ni,chunk) instead of 6.
// CTA tile 128(j) x 128(i), 512 thr (16 warps, 4x4 of 32x32), K-chunk 32,
// 3-stage cp.async, one __syncthreads per chunk.
// SMEM buffer (32KB): Ahh 8K | Bhh 8K | A8h 4K | A8l 4K | B8h 4K | B8l 4K.
// fp16 rows 64B, swz c^=(x>>1)&3;  int8 rows 32B, swz c^=(x>>2)&1.
// ---------------------------------------------------------------------------
#define SMEM_DYN (3 * 32768)

template<int MODE>
__global__ void __launch_bounds__(512)
gemm_hyb_kernel()
{
    constexpr int C   = MODE ? 2048 : 1024;
    constexpr int NCH = C / 32;
    constexpr int TI  = MODE ? 3 : 1;
    constexpr int SI  = MODE ? 2 : 0;

    extern __shared__ __align__(16) char sm[];

    const int tid  = threadIdx.x;
    const int lane = tid & 31;
    const int wid  = tid >> 5;
    const int wj   = wid >> 2;           // 0..3 (32 rows each)
    const int wi   = wid & 3;            // 0..3 (32 cols each)
    const int b  = blockIdx.z;
    const int i0 = blockIdx.x * 128;
    const int j0 = blockIdx.y * 128;

    const __half* Ahp = MODE ? g_h4t : g_h3t;
    const __half* Bhp = MODE ? g_h4s : g_h3s;
    const int8_t* A8h = MODE ? g_q4t[0] : g_q3t[0];
    const int8_t* A8l = MODE ? g_q4t[1] : g_q3t[1];
    const int8_t* B8h = MODE ? g_q4s[0] : g_q3s[0];
    const int8_t* B8l = MODE ? g_q4s[1] : g_q3s[1];

    const uint32_t sb0 = su32(sm);

    // cp.async: fp16 -> row=tid>>2, one 16B chunk c=tid&3 per plane (2 planes)
    const int rF = tid >> 2, cF = tid & 3;
    const uint32_t dF = (uint32_t)(rF * 64) + ((((uint32_t)cF ^ ((rF >> 1) & 3)) & 3u) << 4);
    const size_t rowFA = ((size_t)b * HW + j0 + rF) * C;
    const size_t rowFB = ((size_t)b * HW + i0 + rF) * C;
    // int8 -> row = tid&127, plane sel = tid>>7 (0:A8h 1:A8l 2:B8h 3:B8l), 2 halves
    const int r8 = tid & 127, sel = tid >> 7;
    const int8_t* p8 = (sel == 0) ? A8h : (sel == 1) ? A8l : (sel == 2) ? B8h : B8l;
    const size_t row8 = ((size_t)b * HW + ((sel < 2) ? j0 : i0) + r8) * C;
    const uint32_t d8base = (uint32_t)(16384 + sel * 4096 + r8 * 32);
    const uint32_t sw8 = (uint32_t)((r8 >> 2) & 1);

    // fp16 ldmatrix components (R12-proven)
    uint32_t aoffF[2], aSwF[2];
#pragma unroll
    for (int mi = 0; mi < 2; ++mi) {
        int r = wj * 32 + mi * 16 + (lane & 15);
        aoffF[mi] = (uint32_t)(r * 64);
        aSwF[mi]  = (uint32_t)((r >> 1) & 3);
    }
    const uint32_t hi16 = (uint32_t)((lane >> 4) & 1);
    uint32_t boff4[2], bSw4[2];
#pragma unroll
    for (int np = 0; np < 2; ++np) {
        int r = wi * 32 + (2 * np + ((lane >> 4) & 1)) * 8 + (lane & 7);
        boff4[np] = (uint32_t)(r * 64);
        bSw4[np]  = (uint32_t)((r >> 1) & 3);
    }
    const uint32_t khB = (uint32_t)((lane >> 3) & 1);

    // int8 ldmatrix components (R10-proven)
    uint32_t aoff8[2], aSw8[2];
#pragma unroll
    for (int mi = 0; mi < 2; ++mi) {
        int r = wj * 32 + mi * 16 + (lane & 15);
        aoff8[mi] = (uint32_t)(r * 32);
        aSw8[mi]  = (uint32_t)((r >> 2) & 1);
    }
    const uint32_t aCh8 = (uint32_t)(lane >> 4);
    const int ln = lane & 15;
    uint32_t boff8[4], bSw8[4];
#pragma unroll
    for (int ni = 0; ni < 4; ++ni) {
        int r = wi * 32 + ni * 8 + (ln & 7);
        boff8[ni] = (uint32_t)(r * 32);
        bSw8[ni]  = (uint32_t)((r >> 2) & 1);
    }
    const uint32_t bCh8 = (uint32_t)((ln >> 3) & 1);

    float accH[2][4][4];
    int   accC[2][4][4];
#pragma unroll
    for (int mi = 0; mi < 2; ++mi)
#pragma unroll
        for (int ni = 0; ni < 4; ++ni)
#pragma unroll
            for (int e = 0; e < 4; ++e) { accH[mi][ni][e] = 0.f; accC[mi][ni][e] = 0; }

    auto issue = [&](int t, int buf) {
        const uint32_t db = sb0 + (uint32_t)buf * 32768u;
        const size_t k = (size_t)t * 32;
        cpasync16(db + dF,          Ahp + rowFA + k + cF * 8);
        cpasync16(db + 8192u + dF,  Bhp + rowFB + k + cF * 8);
#pragma unroll
        for (int h = 0; h < 2; ++h) {
            uint32_t d8 = db + d8base + ((((uint32_t)h ^ sw8) & 1u) << 4);
            cpasync16(d8, p8 + row8 + k + h * 16);
        }
        cp_commit();
    };

    issue(0, 0);
    issue(1, 1);

    int bcur = 0;
    for (int t = 0; t < NCH; ++t) {
        if (t + 1 < NCH) cp_wait1(); else cp_wait0();
        __syncthreads();
        if (t + 2 < NCH) {
            int bn = bcur + 2; if (bn >= 3) bn -= 3;
            issue(t + 2, bn);
        }

        const uint32_t sb = sb0 + (uint32_t)bcur * 32768u;

        // ---- fp16 main term ----
#pragma unroll
        for (int ks = 0; ks < 2; ++ks) {
            uint32_t ah[2][4];
#pragma unroll
            for (int mi = 0; mi < 2; ++mi)
                ldmx4(ah[mi], sb + aoffF[mi] + ((((uint32_t)(2 * ks) + hi16) ^ aSwF[mi]) << 4));
#pragma unroll
            for (int np = 0; np < 2; ++np) {
                uint32_t bq[4];
                ldmx4(bq, sb + 8192u + boff4[np] + ((((uint32_t)(2 * ks) + khB) ^ bSw4[np]) << 4));
#pragma unroll
                for (int sub = 0; sub < 2; ++sub)
#pragma unroll
                    for (int mi = 0; mi < 2; ++mi)
                        mma16816(accH[mi][np * 2 + sub], ah[mi], &bq[2 * sub]);
            }
        }

        // ---- int8 correction terms (shared accumulator) ----
        {
            uint32_t a8h[2][4], a8l[2][4];
#pragma unroll
            for (int mi = 0; mi < 2; ++mi) {
                uint32_t adr = sb + 16384u + aoff8[mi] + ((aCh8 ^ aSw8[mi]) << 4);
                ldmx4(a8h[mi], adr);
                ldmx4(a8l[mi], adr + 4096u);
            }
#pragma unroll
            for (int ni = 0; ni < 4; ++ni) {
                uint32_t b8h[2], b8l[2];
                uint32_t badr = sb + 24576u + boff8[ni] + ((bCh8 ^ bSw8[ni]) << 4);
                ldmx2(b8h, badr);
                ldmx2(b8l, badr + 4096u);
#pragma unroll
                for (int mi = 0; mi < 2; ++mi) {
                    imma16832(accC[mi][ni], a8h[mi], b8l);
                    imma16832(accC[mi][ni], a8l[mi], b8h);
                }
            }
        }
        if (++bcur == 3) bcur = 0;
    }

    // ---- epilogue: fold corrections, scale, relu, store ----
    const float* invT = g_inv[TI] + (size_t)b * HW;
    const float* invS = g_inv[SI] + (size_t)b * HW;
    const int gid = lane >> 2, tig = lane & 3;
    const int jb = j0 + wj * 32 + gid;
    const int ib = i0 + wi * 32 + tig * 2;

    float tS[2][2];
#pragma unroll
    for (int mi = 0; mi < 2; ++mi) {
        tS[mi][0] = __ldg(invT + jb + mi * 16);
        tS[mi][1] = __ldg(invT + jb + mi * 16 + 8);
    }
    float2 sS[4];
#pragma unroll
    for (int ni = 0; ni < 4; ++ni)
        sS[ni] = *reinterpret_cast<const float2*>(invS + ib + ni * 8);

#pragma unroll
    for (int mi = 0; mi < 2; ++mi) {
        const int j = jb + mi * 16;
        const size_t row0 = ((size_t)b * HW + j) * HW;
        const size_t row8g = row0 + (size_t)8 * HW;
#pragma unroll
        for (int ni = 0; ni < 4; ++ni) {
            const int i = ib + ni * 8;
            float d0 = fmaf((float)accC[mi][ni][0], SC_INV, accH[mi][ni][0]);
            float d1 = fmaf((float)accC[mi][ni][1], SC_INV, accH[mi][ni][1]);
            float d2 = fmaf((float)accC[mi][ni][2], SC_INV, accH[mi][ni][2]);
            float d3 = fmaf((float)accC[mi][ni][3], SC_INV, accH[mi][ni][3]);
            float c0 = fmaxf(d0 * tS[mi][0] * sS[ni].x, 0.f);
            float c1 = fmaxf(d1 * tS[mi][0] * sS[ni].y, 0.f);
            float c2 = fmaxf(d2 * tS[mi][1] * sS[ni].x, 0.f);
            float c3 = fmaxf(d3 * tS[mi][1] * sS[ni].y, 0.f);
            if (MODE == 0) {
                *reinterpret_cast<float2*>(&g_M[row0 + i])  = make_float2(c0, c1);
                *reinterpret_cast<float2*>(&g_M[row8g + i]) = make_float2(c2, c3);
            } else {
                float2 o0 = *reinterpret_cast<const float2*>(&g_M[row0 + i]);
                float2 o8 = *reinterpret_cast<const float2*>(&g_M[row8g + i]);
                float m0 = o0.x * c0, m1 = o0.y * c1;
                float m2 = o8.x * c2, m3 = o8.y * c3;
                *reinterpret_cast<float2*>(&g_M[row0 + i])  = make_float2(m0, m1);
                *reinterpret_cast<float2*>(&g_M[row8g + i]) = make_float2(m2, m3);
                const size_t tc0 = ((size_t)b * HW + i) * HW;
                g_MT[tc0 + j]          = m0;
                g_MT[tc0 + HW + j]     = m1;
                g_MT[tc0 + j + 8]      = m2;
                g_MT[tc0 + HW + j + 8] = m3;
            }
        }
    }
}

// ---------------------------------------------------------------------------
// Kernel 3: soft-argmax per column (unchanged).
// ---------------------------------------------------------------------------
__global__ void __launch_bounds__(256)
softargmax_kernel(float* __restrict__ out)
{
    __shared__ float gtab[64];
    __shared__ float redf[8];
    __shared__ int   redi[8];
    __shared__ float bc[2];
    __shared__ float r3[3][8];

    const int pos = blockIdx.x;
    const int b   = blockIdx.y;
    const int dir = blockIdx.z;
    const int tid = threadIdx.x;
    const int lane = tid & 31, wid = tid >> 5;

    const float* row = (dir == 0 ? g_MT : g_M) + ((size_t)b * HW + pos) * HW;

    if (tid < 64) gtab[tid] = expf(-(float)(tid * tid) * (1.0f / 50.0f));

    float xr[16];
    float ss = 0.f;
#pragma unroll
    for (int s = 0; s < 16; ++s) {
        float x = row[tid + s * 256];
        xr[s] = x;
        ss = fmaf(x, x, ss);
    }
    for (int o = 16; o; o >>= 1) ss += __shfl_down_sync(0xffffffffu, ss, o);
    if (lane == 0) redf[wid] = ss;
    __syncthreads();
    if (wid == 0) {
        float v = (lane < 8) ? redf[lane] : 0.f;
        for (int o = 4; o; o >>= 1) v += __shfl_down_sync(0xffffffffu, v, o);
        if (lane == 0) bc[0] = rsqrtf(v + 1e-6f);
    }
    __syncthreads();
    const float invn = bc[0];

    float bvv = -1.f; int bj = HW;
#pragma unroll
    for (int s = 0; s < 16; ++s) {
        float x = xr[s];
        int j = tid + s * 256;
        if (x > bvv) { bvv = x; bj = j; }
    }
    for (int o = 16; o; o >>= 1) {
        float ov = __shfl_down_sync(0xffffffffu, bvv, o);
        int   oj = __shfl_down_sync(0xffffffffu, bj,  o);
        if (ov > bvv || (ov == bvv && oj < bj)) { bvv = ov; bj = oj; }
    }
    __syncthreads();
    if (lane == 0) { redf[wid] = bvv; redi[wid] = bj; }
    __syncthreads();
    if (tid == 0) {
        float bestv = redf[0]; int bestj = redi[0];
        for (int q = 1; q < 8; ++q)
            if (redf[q] > bestv || (redf[q] == bestv && redi[q] < bestj)) {
                bestv = redf[q]; bestj = redi[q];
            }
        redi[0] = bestj;
    }
    __syncthreads();
    const int amax = redi[0];
    const int ax = amax & 63, ay = amax >> 6;

    float cm = -1.f;
#pragma unroll
    for (int s = 0; s < 16; ++s) {
        int j = tid + s * 256;
        int dx = (j & 63) - ax; dx = dx < 0 ? -dx : dx;
        int dy = (j >> 6) - ay; dy = dy < 0 ? -dy : dy;
        float g = gtab[dx] * gtab[dy];
        float c = (g < 1e-6f) ? -1.f : g * xr[s] * invn;
        xr[s] = c;
        cm = fmaxf(cm, c);
    }
    for (int o = 16; o; o >>= 1) cm = fmaxf(cm, __shfl_down_sync(0xffffffffu, cm, o));
    __syncthreads();
    if (lane == 0) redf[wid] = cm;
    __syncthreads();
    if (wid == 0) {
        float v = (lane < 8) ? redf[lane] : -1.f;
        for (int o = 4; o; o >>= 1) v = fmaxf(v, __shfl_down_sync(0xffffffffu, v, o));
        if (lane == 0) bc[1] = v;
    }
    __syncthreads();
    const float m  = bc[1];
    const float e0 = __expf(-50.f * m);

    float se = 0.f, sx = 0.f, sy = 0.f;
#pragma unroll
    for (int s = 0; s < 16; ++s) {
        float c = xr[s];
        if (c >= 0.f) {
            int j = tid + s * 256;
            float e = __expf(50.f * (c - m)) - e0;
            float xn = fmaf((float)(j & 63), 2.f / 63.f, -1.f);
            float yn = fmaf((float)(j >> 6), 2.f / 63.f, -1.f);
            se += e;
            sx = fmaf(e, xn, sx);
            sy = fmaf(e, yn, sy);
        }
    }
    for (int o = 16; o; o >>= 1) {
        se += __shfl_down_sync(0xffffffffu, se, o);
        sx += __shfl_down_sync(0xffffffffu, sx, o);
        sy += __shfl_down_sync(0xffffffffu, sy, o);
    }
    if (lane == 0) { r3[0][wid] = se; r3[1][wid] = sx; r3[2][wid] = sy; }
    __syncthreads();
    if (tid == 0) {
        float tse = 0.f, tsx = 0.f, tsy = 0.f;
        for (int q = 0; q < 8; ++q) { tse += r3[0][q]; tsx += r3[1][q]; tsy += r3[2][q]; }
        float denom = tse + 4096.f * e0;
        float gx = tsx / denom;
        float gy = tsy / denom;
        size_t ob = (size_t)dir * 32768 + (((size_t)b * 64 + (pos >> 6)) * 64 + (pos & 63)) * 2;
        out[ob]     = gx;
        out[ob + 1] = gy;
    }
}

// ---------------------------------------------------------------------------
__global__ void zero_kernel(float* __restrict__ out)
{
    int i = blockIdx.x * blockDim.x + threadIdx.x;
    int base = (i < 16384) ? 16384 : 49152;
    out[base + (i & 16383)] = 0.f;
}

// ---------------------------------------------------------------------------
extern "C" void kernel_launch(void* const* d_in, const int* in_sizes, int n_in,
                              void* d_out, int out_size)
{
    const float* s3 = (const float*)d_in[0];
    const float* t3 = (const float*)d_in[1];
    const float* s4 = (const float*)d_in[2];
    const float* t4 = (const float*)d_in[3];
    float* out = (float*)d_out;

    cudaFuncSetAttribute(gemm_hyb_kernel<0>, cudaFuncAttributeMaxDynamicSharedMemorySize, SMEM_DYN);
    cudaFuncSetAttribute(gemm_hyb_kernel<1>, cudaFuncAttributeMaxDynamicSharedMemorySize, SMEM_DYN);

    norm_kernel<<<dim3(32, 4), 256>>>(s3, t3, s4, t4);
    split_kernel<<<dim3(64, 16, NB), 256>>>(s3, 0, 1024);
    split_kernel<<<dim3(64, 16, NB), 256>>>(t3, 1, 1024);
    gemm_hyb_kernel<0><<<dim3(32, 32, NB), 512, SMEM_DYN>>>();
    split_kernel<<<dim3(64, 32, NB), 256>>>(s4, 2, 2048);
    split_kernel<<<dim3(64, 32, NB), 256>>>(t4, 3, 2048);
    gemm_hyb_kernel<1><<<dim3(32, 32, NB), 512, SMEM_DYN>>>();
    softargmax_kernel<<<dim3(HW, NB, 2), 256>>>(out);
    zero_kernel<<<64, 512>>>(out);
}

// round 15
// speedup vs baseline: 4.5412x; 4.5412x over previous
#include <cuda_runtime.h>
#include <cuda_fp16.h>
#include <stdint.h>
#include <math.h>

#define HW 4096
#define NB 2

__device__ float g_M [(size_t)NB * HW * HW];   // M[b][j][i]
__device__ float g_MT[(size_t)NB * HW * HW];   // M[b][i][j]
__device__ float g_inv[4][NB * HW];            // 0:src3 1:tgt3 2:src4 3:tgt4

// fp16 hi/lo limb planes, K-major: [limb][b][pos][C]
#define N3 ((size_t)NB * HW * 1024)
#define N4 ((size_t)NB * HW * 2048)
__device__ __align__(256) __half g_h3s[2][N3];
__device__ __align__(256) __half g_h3t[2][N3];
__device__ __align__(256) __half g_h4s[2][N4];
__device__ __align__(256) __half g_h4t[2][N4];

// ---------------------------------------------------------------------------
// PTX helpers (base sm_80 features only -> legal at compute_103)
// ---------------------------------------------------------------------------
__device__ __forceinline__ uint32_t su32(const void* p) {
    uint32_t a;
    asm("{ .reg .u64 t; cvta.to.shared.u64 t, %1; cvt.u32.u64 %0, t; }" : "=r"(a) : "l"(p));
    return a;
}
__device__ __forceinline__ void ldmx4(uint32_t* r, uint32_t a) {
    asm volatile("ldmatrix.sync.aligned.m8n8.x4.shared.b16 {%0,%1,%2,%3}, [%4];"
                 : "=r"(r[0]), "=r"(r[1]), "=r"(r[2]), "=r"(r[3]) : "r"(a));
}
__device__ __forceinline__ void mma16816(float* d, const uint32_t* a, const uint32_t* b) {
    asm volatile(
        "mma.sync.aligned.m16n8k16.row.col.f32.f16.f16.f32 "
        "{%0,%1,%2,%3}, {%4,%5,%6,%7}, {%8,%9}, {%0,%1,%2,%3};"
        : "+f"(d[0]), "+f"(d[1]), "+f"(d[2]), "+f"(d[3])
        : "r"(a[0]), "r"(a[1]), "r"(a[2]), "r"(a[3]), "r"(b[0]), "r"(b[1]));
}
__device__ __forceinline__ void cpasync16(uint32_t dst, const void* src) {
    asm volatile("cp.async.cg.shared.global [%0], [%1], 16;" :: "r"(dst), "l"(src));
}
__device__ __forceinline__ void cp_commit() { asm volatile("cp.async.commit_group;"); }
__device__ __forceinline__ void cp_wait1()  { asm volatile("cp.async.wait_group 1;"); }
__device__ __forceinline__ void cp_wait0()  { asm volatile("cp.async.wait_group 0;"); }

// ---------------------------------------------------------------------------
// Kernel 1: per-position inverse channel norms.
// ---------------------------------------------------------------------------
__global__ void norm_kernel(const float* __restrict__ s3, const float* __restrict__ t3,
                            const float* __restrict__ s4, const float* __restrict__ t4)
{
    int gid   = blockIdx.x * 256 + threadIdx.x;
    int which = blockIdx.y;
    const float* x; int C;
    if      (which == 0) { x = s3; C = 1024; }
    else if (which == 1) { x = t3; C = 1024; }
    else if (which == 2) { x = s4; C = 2048; }
    else                 { x = t4; C = 2048; }

    int b = gid >> 12, pos = gid & (HW - 1);
    const float* p = x + (size_t)b * C * HW + pos;
    float ss0 = 0.f, ss1 = 0.f, ss2 = 0.f, ss3 = 0.f;
    for (int c = 0; c < C; c += 4) {
        float a0 = p[(size_t)(c + 0) * HW];
        float a1 = p[(size_t)(c + 1) * HW];
        float a2 = p[(size_t)(c + 2) * HW];
        float a3 = p[(size_t)(c + 3) * HW];
        ss0 = fmaf(a0, a0, ss0); ss1 = fmaf(a1, a1, ss1);
        ss2 = fmaf(a2, a2, ss2); ss3 = fmaf(a3, a3, ss3);
    }
    g_inv[which][gid] = rsqrtf((ss0 + ss1) + (ss2 + ss3) + 1e-6f);
}

// ---------------------------------------------------------------------------
// Kernel 1b: fp16 hi/lo split + transpose prepass (R12-proven).
// ---------------------------------------------------------------------------
__global__ void __launch_bounds__(256)
split_kernel(const float* __restrict__ in, int which, int C)
{
    __shared__ float tile[64][65];
    __half* hi; __half* lo;
    if      (which == 0) { hi = g_h3s[0]; lo = g_h3s[1]; }
    else if (which == 1) { hi = g_h3t[0]; lo = g_h3t[1]; }
    else if (which == 2) { hi = g_h4s[0]; lo = g_h4s[1]; }
    else                 { hi = g_h4t[0]; lo = g_h4t[1]; }

    const int p0 = blockIdx.x * 64, c0 = blockIdx.y * 64, b = blockIdx.z;
    const float* src = in + (size_t)b * C * HW;
    const int tid = threadIdx.x;

#pragma unroll
    for (int l = 0; l < 16; ++l) {
        int idx = tid + l * 256;
        int c = idx >> 6, p = idx & 63;
        tile[c][p] = src[(size_t)(c0 + c) * HW + p0 + p];
    }
    __syncthreads();

    const int cg = tid & 7;
#pragma unroll
    for (int pass = 0; pass < 2; ++pass) {
        const int p = (tid >> 3) + pass * 32;
        union { __half h[8]; uint4 u; } H, L;
#pragma unroll
        for (int e = 0; e < 8; ++e) {
            float v = tile[cg * 8 + e][p];
            __half h = __float2half_rn(v);
            H.h[e] = h;
            L.h[e] = __float2half_rn(v - __half2float(h));
        }
        size_t o = ((size_t)b * HW + p0 + p) * C + c0 + cg * 8;
        *reinterpret_cast<uint4*>(hi + o) = H.u;
        *reinterpret_cast<uint4*>(lo + o) = L.u;
    }
}

// ---------------------------------------------------------------------------
// Kernel 2: SINGLE-TERM fp16 mma.sync GEMM (ah*bh only).  Structure = R12
// minus the lo limbs.  CTA tile 128x128, K-chunk 32, 8 warps of 64x32,
// 3-stage cp.async, one __syncthreads per chunk.
// Buffer (16KB): Ah 8K | Bh 8K.  Row = 64B, 16B chunks swizzled c^=(x>>1)&3.
// ---------------------------------------------------------------------------
#define SMEM_DYN (3 * 16384)

template<int MODE>
__global__ void __launch_bounds__(256, 2)
gemm_hmma_kernel()
{
    constexpr int C   = MODE ? 2048 : 1024;
    constexpr int NCH = C / 32;
    constexpr int TI  = MODE ? 3 : 1;
    constexpr int SI  = MODE ? 2 : 0;

    extern __shared__ __align__(16) char sm[];

    const int tid  = threadIdx.x;
    const int lane = tid & 31;
    const int wid  = tid >> 5;
    const int wj   = wid >> 2;
    const int wi   = wid & 3;
    const int b  = blockIdx.z;
    const int i0 = blockIdx.x * 128;
    const int j0 = blockIdx.y * 128;

    const __half* Ahp = MODE ? g_h4t[0] : g_h3t[0];
    const __half* Bhp = MODE ? g_h4s[0] : g_h3s[0];

    const uint32_t sb0 = su32(sm);

    const int xa = tid >> 1, cp0 = (tid & 1) * 2;
    const uint32_t swz = (uint32_t)((xa >> 1) & 3);
    const size_t rowA = ((size_t)b * HW + j0 + xa) * C;
    const size_t rowB = ((size_t)b * HW + i0 + xa) * C;

    uint32_t aoff[4], aSw[4];
#pragma unroll
    for (int mi = 0; mi < 4; ++mi) {
        int r = wj * 64 + mi * 16 + (lane & 15);
        aoff[mi] = (uint32_t)(r * 64);
        aSw[mi]  = (uint32_t)((r >> 1) & 3);
    }
    const uint32_t hi16 = (uint32_t)((lane >> 4) & 1);
    uint32_t boff4[2], bSw4[2];
#pragma unroll
    for (int np = 0; np < 2; ++np) {
        int r = wi * 32 + (2 * np + ((lane >> 4) & 1)) * 8 + (lane & 7);
        boff4[np] = (uint32_t)(r * 64);
        bSw4[np]  = (uint32_t)((r >> 1) & 3);
    }
    const uint32_t khB = (uint32_t)((lane >> 3) & 1);

    float acc[4][4][4];
#pragma unroll
    for (int mi = 0; mi < 4; ++mi)
#pragma unroll
        for (int ni = 0; ni < 4; ++ni)
#pragma unroll
            for (int e = 0; e < 4; ++e) acc[mi][ni][e] = 0.f;

    auto issue = [&](int t, int buf) {
        const uint32_t db = sb0 + (uint32_t)buf * 16384u;
        const size_t k = (size_t)t * 32;
#pragma unroll
        for (int c = cp0; c < cp0 + 2; ++c) {
            uint32_t doff = (uint32_t)(xa * 64) + ((((uint32_t)c ^ swz) & 3u) << 4);
            cpasync16(db + doff,          Ahp + rowA + k + c * 8);
            cpasync16(db + 8192u + doff,  Bhp + rowB + k + c * 8);
        }
        cp_commit();
    };

    issue(0, 0);
    issue(1, 1);

    int bcur = 0;
    for (int t = 0; t < NCH; ++t) {
        if (t + 1 < NCH) cp_wait1(); else cp_wait0();
        __syncthreads();
        if (t + 2 < NCH) {
            int bn = bcur + 2; if (bn >= 3) bn -= 3;
            issue(t + 2, bn);
        }

        const uint32_t sb = sb0 + (uint32_t)bcur * 16384u;
#pragma unroll
        for (int ks = 0; ks < 2; ++ks) {
            uint32_t ah[4][4];
#pragma unroll
            for (int mi = 0; mi < 4; ++mi)
                ldmx4(ah[mi], sb + aoff[mi] + ((((uint32_t)(2 * ks) + hi16) ^ aSw[mi]) << 4));
#pragma unroll
            for (int np = 0; np < 2; ++np) {
                uint32_t bq[4];
                ldmx4(bq, sb + 8192u + boff4[np] + ((((uint32_t)(2 * ks) + khB) ^ bSw4[np]) << 4));
#pragma unroll
                for (int sub = 0; sub < 2; ++sub)
#pragma unroll
                    for (int mi = 0; mi < 4; ++mi)
                        mma16816(acc[mi][np * 2 + sub], ah[mi], &bq[2 * sub]);
            }
        }
        if (++bcur == 3) bcur = 0;
    }

    // ---- epilogue (R12-proven) ----
    const float* invT = g_inv[TI] + (size_t)b * HW;
    const float* invS = g_inv[SI] + (size_t)b * HW;
    const int gid = lane >> 2, tig = lane & 3;
    const int jb = j0 + wj * 64 + gid;
    const int ib = i0 + wi * 32 + tig * 2;

    float tS[4][2];
#pragma unroll
    for (int mi = 0; mi < 4; ++mi) {
        tS[mi][0] = __ldg(invT + jb + mi * 16);
        tS[mi][1] = __ldg(invT + jb + mi * 16 + 8);
    }
    float2 sS[4];
#pragma unroll
    for (int ni = 0; ni < 4; ++ni)
        sS[ni] = *reinterpret_cast<const float2*>(invS + ib + ni * 8);

#pragma unroll
    for (int mi = 0; mi < 4; ++mi) {
        const int j = jb + mi * 16;
        const size_t row0 = ((size_t)b * HW + j) * HW;
        const size_t row8 = row0 + (size_t)8 * HW;
#pragma unroll
        for (int ni = 0; ni < 4; ++ni) {
            const int i = ib + ni * 8;
            float c0 = fmaxf(acc[mi][ni][0] * tS[mi][0] * sS[ni].x, 0.f);
            float c1 = fmaxf(acc[mi][ni][1] * tS[mi][0] * sS[ni].y, 0.f);
            float c2 = fmaxf(acc[mi][ni][2] * tS[mi][1] * sS[ni].x, 0.f);
            float c3 = fmaxf(acc[mi][ni][3] * tS[mi][1] * sS[ni].y, 0.f);
            if (MODE == 0) {
                *reinterpret_cast<float2*>(&g_M[row0 + i]) = make_float2(c0, c1);
                *reinterpret_cast<float2*>(&g_M[row8 + i]) = make_float2(c2, c3);
            } else {
                float2 o0 = *reinterpret_cast<const float2*>(&g_M[row0 + i]);
                float2 o8 = *reinterpret_cast<const float2*>(&g_M[row8 + i]);
                float m0 = o0.x * c0, m1 = o0.y * c1;
                float m2 = o8.x * c2, m3 = o8.y * c3;
                *reinterpret_cast<float2*>(&g_M[row0 + i]) = make_float2(m0, m1);
                *reinterpret_cast<float2*>(&g_M[row8 + i]) = make_float2(m2, m3);
                const size_t tc0 = ((size_t)b * HW + i) * HW;
                g_MT[tc0 + j]          = m0;
                g_MT[tc0 + HW + j]     = m1;
                g_MT[tc0 + j + 8]      = m2;
                g_MT[tc0 + HW + j + 8] = m3;
            }
        }
    }
}

// ---------------------------------------------------------------------------
// Exact dot of two feature columns from the hi+lo fp16 planes (error ~2^-22).
// Warp-collective; result valid on lane 0.
// ---------------------------------------------------------------------------
__device__ __forceinline__ float warp_dot(const __half* __restrict__ Th,
                                          const __half* __restrict__ Tl,
                                          const __half* __restrict__ Sh,
                                          const __half* __restrict__ Sl,
                                          size_t rt, size_t rs, int C, int lane)
{
    const __half2* ah = reinterpret_cast<const __half2*>(Th + rt);
    const __half2* al = reinterpret_cast<const __half2*>(Tl + rt);
    const __half2* bh = reinterpret_cast<const __half2*>(Sh + rs);
    const __half2* bl = reinterpret_cast<const __half2*>(Sl + rs);
    float acc = 0.f;
    for (int c = lane; c < C / 2; c += 32) {
        float2 a0 = __half22float2(ah[c]);
        float2 a1 = __half22float2(al[c]);
        float2 b0 = __half22float2(bh[c]);
        float2 b1 = __half22float2(bl[c]);
        acc = fmaf(a0.x + a1.x, b0.x + b1.x, acc);
        acc = fmaf(a0.y + a1.y, b0.y + b1.y, acc);
    }
    for (int o = 16; o; o >>= 1) acc += __shfl_down_sync(0xffffffffu, acc, o);
    return acc;
}

// ---------------------------------------------------------------------------
// Kernel 3: soft-argmax per column + EXACT argmax refinement.
// Approx M has ~1e-4 (normalized) error at the top; candidates within
// 1e-3*colnorm of the approx max are recomputed exactly from the hi/lo
// feature planes, restoring the reference argmax.
// ---------------------------------------------------------------------------
__global__ void __launch_bounds__(256)
softargmax_kernel(float* __restrict__ out)
{
    __shared__ float gtab[64];
    __shared__ float redf[8];
    __shared__ int   redi[8];
    __shared__ float bc[2];
    __shared__ float r3[3][8];
    __shared__ int   candj[32];
    __shared__ float candv[32];
    __shared__ int   candn;
    __shared__ float bestvS;

    const int pos = blockIdx.x;
    const int b   = blockIdx.y;
    const int dir = blockIdx.z;
    const int tid = threadIdx.x;
    const int lane = tid & 31, wid = tid >> 5;

    const float* row = (dir == 0 ? g_MT : g_M) + ((size_t)b * HW + pos) * HW;

    if (tid < 64) gtab[tid] = expf(-(float)(tid * tid) * (1.0f / 50.0f));
    if (tid == 0) candn = 0;

    // ---- pass 1: load raw values + sum of squares
    float xr[16];
    float ss = 0.f;
#pragma unroll
    for (int s = 0; s < 16; ++s) {
        float x = row[tid + s * 256];
        xr[s] = x;
        ss = fmaf(x, x, ss);
    }
    for (int o = 16; o; o >>= 1) ss += __shfl_down_sync(0xffffffffu, ss, o);
    if (lane == 0) redf[wid] = ss;
    __syncthreads();
    if (wid == 0) {
        float v = (lane < 8) ? redf[lane] : 0.f;
        for (int o = 4; o; o >>= 1) v += __shfl_down_sync(0xffffffffu, v, o);
        if (lane == 0) bc[0] = rsqrtf(v + 1e-6f);
    }
    __syncthreads();
    const float invn = bc[0];

    // ---- pass 2: approx argmax
    float bvv = -1.f; int bj = HW;
#pragma unroll
    for (int s = 0; s < 16; ++s) {
        float x = xr[s];
        int j = tid + s * 256;
        if (x > bvv) { bvv = x; bj = j; }
    }
    for (int o = 16; o; o >>= 1) {
        float ov = __shfl_down_sync(0xffffffffu, bvv, o);
        int   oj = __shfl_down_sync(0xffffffffu, bj,  o);
        if (ov > bvv || (ov == bvv && oj < bj)) { bvv = ov; bj = oj; }
    }
    __syncthreads();
    if (lane == 0) { redf[wid] = bvv; redi[wid] = bj; }
    __syncthreads();
    if (tid == 0) {
        float bestv = redf[0]; int bestj = redi[0];
        for (int q = 1; q < 8; ++q)
            if (redf[q] > bestv || (redf[q] == bestv && redi[q] < bestj)) {
                bestv = redf[q]; bestj = redi[q];
            }
        redi[0] = bestj;
        bestvS  = bestv;
    }
    __syncthreads();

    // ---- exact argmax refinement ----
    {
        const float thr = bestvS - 1e-3f / invn;   // 1e-3 in normalized units
#pragma unroll
        for (int s = 0; s < 16; ++s) {
            if (xr[s] >= thr) {
                int k = atomicAdd(&candn, 1);
                if (k < 32) candj[k] = tid + s * 256;
            }
        }
        __syncthreads();
        const int nc = candn;
        if (nc > 1 && nc <= 32) {
            for (int c = wid; c < nc; c += 8) {
                int jc = candj[c];
                int jt = (dir == 0) ? jc : pos;    // target-feature column
                int js = (dir == 0) ? pos : jc;    // source-feature column
                size_t rt3 = ((size_t)b * HW + jt) * 1024;
                size_t rs3 = ((size_t)b * HW + js) * 1024;
                size_t rt4 = ((size_t)b * HW + jt) * 2048;
                size_t rs4 = ((size_t)b * HW + js) * 2048;
                float d3 = warp_dot(g_h3t[0], g_h3t[1], g_h3s[0], g_h3s[1], rt3, rs3, 1024, lane);
                float d4 = warp_dot(g_h4t[0], g_h4t[1], g_h4s[0], g_h4s[1], rt4, rs4, 2048, lane);
                if (lane == 0) {
                    float c3 = d3 * g_inv[1][b * HW + jt] * g_inv[0][b * HW + js];
                    float c4 = d4 * g_inv[3][b * HW + jt] * g_inv[2][b * HW + js];
                    candv[c] = fmaxf(c3, 0.f) * fmaxf(c4, 0.f);
                }
            }
            __syncthreads();
            if (tid == 0) {
                float bv = -1.f; int bjx = HW;
                for (int c = 0; c < nc; ++c)
                    if (candv[c] > bv || (candv[c] == bv && candj[c] < bjx)) {
                        bv = candv[c]; bjx = candj[c];
                    }
                redi[0] = bjx;
            }
            __syncthreads();
        }
    }
    const int amax = redi[0];
    const int ax = amax & 63, ay = amax >> 6;

    // ---- pass 3: gaussian mask (dx constant per thread) ----
    const int xbase = tid & 63, ybase = tid >> 6;
    int dxc = xbase - ax; dxc = dxc < 0 ? -dxc : dxc;
    const float gx = gtab[dxc];
    float cm = -1.f;
#pragma unroll
    for (int s = 0; s < 16; ++s) {
        int dy = ybase + 4 * s - ay; dy = dy < 0 ? -dy : dy;
        float g = gx * gtab[dy];
        float c = (g < 1e-6f) ? -1.f : g * xr[s] * invn;
        xr[s] = c;
        cm = fmaxf(cm, c);
    }
    for (int o = 16; o; o >>= 1) cm = fmaxf(cm, __shfl_down_sync(0xffffffffu, cm, o));
    __syncthreads();
    if (lane == 0) redf[wid] = cm;
    __syncthreads();
    if (wid == 0) {
        float v = (lane < 8) ? redf[lane] : -1.f;
        for (int o = 4; o; o >>= 1) v = fmaxf(v, __shfl_down_sync(0xffffffffu, v, o));
        if (lane == 0) bc[1] = v;
    }
    __syncthreads();
    const float m  = bc[1];
    const float e0 = __expf(-50.f * m);

    // ---- pass 4: stable softmax + soft-argmax sums (xn constant per thread)
    const float xn = fmaf((float)xbase, 2.f / 63.f, -1.f);
    float se = 0.f, sy = 0.f;
#pragma unroll
    for (int s = 0; s < 16; ++s) {
        float c = xr[s];
        if (c >= 0.f) {
            float e = __expf(50.f * (c - m)) - e0;
            float yn = fmaf((float)(ybase + 4 * s), 2.f / 63.f, -1.f);
            se += e;
            sy = fmaf(e, yn, sy);
        }
    }
    float sx = xn * se;
    for (int o = 16; o; o >>= 1) {
        se += __shfl_down_sync(0xffffffffu, se, o);
        sx += __shfl_down_sync(0xffffffffu, sx, o);
        sy += __shfl_down_sync(0xffffffffu, sy, o);
    }
    if (lane == 0) { r3[0][wid] = se; r3[1][wid] = sx; r3[2][wid] = sy; }
    __syncthreads();
    if (tid == 0) {
        float tse = 0.f, tsx = 0.f, tsy = 0.f;
        for (int q = 0; q < 8; ++q) { tse += r3[0][q]; tsx += r3[1][q]; tsy += r3[2][q]; }
        float denom = tse + 4096.f * e0;
        float gxo = tsx / denom;
        float gyo = tsy / denom;
        size_t ob = (size_t)dir * 32768 + (((size_t)b * 64 + (pos >> 6)) * 64 + (pos & 63)) * 2;
        out[ob]     = gxo;
        out[ob + 1] = gyo;
    }
}

// ---------------------------------------------------------------------------
__global__ void zero_kernel(float* __restrict__ out)
{
    int i = blockIdx.x * blockDim.x + threadIdx.x;
    int base = (i < 16384) ? 16384 : 49152;
    out[base + (i & 16383)] = 0.f;
}

// ---------------------------------------------------------------------------
extern "C" void kernel_launch(void* const* d_in, const int* in_sizes, int n_in,
                              void* d_out, int out_size)
{
    const float* s3 = (const float*)d_in[0];
    const float* t3 = (const float*)d_in[1];
    const float* s4 = (const float*)d_in[2];
    const float* t4 = (const float*)d_in[3];
    float* out = (float*)d_out;

    cudaFuncSetAttribute(gemm_hmma_kernel<0>, cudaFuncAttributeMaxDynamicSharedMemorySize, SMEM_DYN);
    cudaFuncSetAttribute(gemm_hmma_kernel<1>, cudaFuncAttributeMaxDynamicSharedMemorySize, SMEM_DYN);

    norm_kernel<<<dim3(32, 4), 256>>>(s3, t3, s4, t4);
    split_kernel<<<dim3(64, 16, NB), 256>>>(s3, 0, 1024);
    split_kernel<<<dim3(64, 16, NB), 256>>>(t3, 1, 1024);
    split_kernel<<<dim3(64, 32, NB), 256>>>(s4, 2, 2048);
    split_kernel<<<dim3(64, 32, NB), 256>>>(t4, 3, 2048);
    gemm_hmma_kernel<0><<<dim3(32, 32, NB), 256, SMEM_DYN>>>();
    gemm_hmma_kernel<1><<<dim3(32, 32, NB), 256, SMEM_DYN>>>();
    softargmax_kernel<<<dim3(HW, NB, 2), 256>>>(out);
    zero_kernel<<<64, 512>>>(out);
}

// round 17
// speedup vs baseline: 4.8880x; 1.0764x over previous
#include <cuda_runtime.h>
#include <cuda_fp16.h>
#include <stdint.h>
#include <math.h>

#define HW 4096
#define NB 2

__device__ float g_M [(size_t)NB * HW * HW];   // M[b][j][i]
__device__ float g_MT[(size_t)NB * HW * HW];   // M[b][i][j]
__device__ float g_inv[4][NB * HW];            // 0:src3 1:tgt3 2:src4 3:tgt4
__device__ float g_ssq[4][NB * HW];            // sum of squares accumulators

// fp16 hi/lo limb planes, K-major: [limb][b][pos][C]
#define N3 ((size_t)NB * HW * 1024)
#define N4 ((size_t)NB * HW * 2048)
__device__ __align__(256) __half g_h3s[2][N3];
__device__ __align__(256) __half g_h3t[2][N3];
__device__ __align__(256) __half g_h4s[2][N4];
__device__ __align__(256) __half g_h4t[2][N4];

// ---------------------------------------------------------------------------
// PTX helpers (base sm_80 features only -> legal at compute_103)
// ---------------------------------------------------------------------------
__device__ __forceinline__ uint32_t su32(const void* p) {
    uint32_t a;
    asm("{ .reg .u64 t; cvta.to.shared.u64 t, %1; cvt.u32.u64 %0, t; }" : "=r"(a) : "l"(p));
    return a;
}
__device__ __forceinline__ void ldmx4(uint32_t* r, uint32_t a) {
    asm volatile("ldmatrix.sync.aligned.m8n8.x4.shared.b16 {%0,%1,%2,%3}, [%4];"
                 : "=r"(r[0]), "=r"(r[1]), "=r"(r[2]), "=r"(r[3]) : "r"(a));
}
__device__ __forceinline__ void mma16816(float* d, const uint32_t* a, const uint32_t* b) {
    asm volatile(
        "mma.sync.aligned.m16n8k16.row.col.f32.f16.f16.f32 "
        "{%0,%1,%2,%3}, {%4,%5,%6,%7}, {%8,%9}, {%0,%1,%2,%3};"
        : "+f"(d[0]), "+f"(d[1]), "+f"(d[2]), "+f"(d[3])
        : "r"(a[0]), "r"(a[1]), "r"(a[2]), "r"(a[3]), "r"(b[0]), "r"(b[1]));
}
__device__ __forceinline__ void cpasync16(uint32_t dst, const void* src) {
    asm volatile("cp.async.cg.shared.global [%0], [%1], 16;" :: "r"(dst), "l"(src));
}
__device__ __forceinline__ void cp_commit() { asm volatile("cp.async.commit_group;"); }
__device__ __forceinline__ void cp_wait2()  { asm volatile("cp.async.wait_group 2;"); }
__device__ __forceinline__ void cp_wait1()  { asm volatile("cp.async.wait_group 1;"); }
__device__ __forceinline__ void cp_wait0()  { asm volatile("cp.async.wait_group 0;"); }

// ---------------------------------------------------------------------------
// Kernel 0: prep — zero the sumsq accumulators and the flow outputs.
// ---------------------------------------------------------------------------
__global__ void prep_kernel(float* __restrict__ out)
{
    int i = blockIdx.x * blockDim.x + threadIdx.x;      // 0..65535
    if (i < 32768) {
        (&g_ssq[0][0])[i] = 0.f;
    } else {
        int k = i - 32768;                              // 0..32767
        int base = (k < 16384) ? 16384 : 49152;
        out[base + (k & 16383)] = 0.f;
    }
}

// ---------------------------------------------------------------------------
// Kernel 1: fp16 hi/lo split + transpose prepass, fused norm partial sums.
// ---------------------------------------------------------------------------
__global__ void __launch_bounds__(256)
split_kernel(const float* __restrict__ in, int which, int C)
{
    __shared__ float tile[64][65];
    __half* hi; __half* lo;
    if      (which == 0) { hi = g_h3s[0]; lo = g_h3s[1]; }
    else if (which == 1) { hi = g_h3t[0]; lo = g_h3t[1]; }
    else if (which == 2) { hi = g_h4s[0]; lo = g_h4s[1]; }
    else                 { hi = g_h4t[0]; lo = g_h4t[1]; }

    const int p0 = blockIdx.x * 64, c0 = blockIdx.y * 64, b = blockIdx.z;
    const float* src = in + (size_t)b * C * HW;
    const int tid = threadIdx.x;
    const int lane = tid & 31;

#pragma unroll
    for (int l = 0; l < 16; ++l) {
        int idx = tid + l * 256;
        int c = idx >> 6, p = idx & 63;
        tile[c][p] = src[(size_t)(c0 + c) * HW + p0 + p];
    }
    __syncthreads();

    const int cg = tid & 7;
#pragma unroll
    for (int pass = 0; pass < 2; ++pass) {
        const int p = (tid >> 3) + pass * 32;
        union { __half h[8]; uint4 u; } H, L;
        float v2 = 0.f;
#pragma unroll
        for (int e = 0; e < 8; ++e) {
            float v = tile[cg * 8 + e][p];
            v2 = fmaf(v, v, v2);
            __half h = __float2half_rn(v);
            H.h[e] = h;
            L.h[e] = __float2half_rn(v - __half2float(h));
        }
        size_t o = ((size_t)b * HW + p0 + p) * C + c0 + cg * 8;
        *reinterpret_cast<uint4*>(hi + o) = H.u;
        *reinterpret_cast<uint4*>(lo + o) = L.u;
        v2 += __shfl_down_sync(0xffffffffu, v2, 4, 8);
        v2 += __shfl_down_sync(0xffffffffu, v2, 2, 8);
        v2 += __shfl_down_sync(0xffffffffu, v2, 1, 8);
        if ((lane & 7) == 0)
            atomicAdd(&g_ssq[which][(size_t)b * HW + p0 + p], v2);
    }
}

// ---------------------------------------------------------------------------
// Kernel 1c: finalize inverse norms.
// ---------------------------------------------------------------------------
__global__ void inv_kernel()
{
    int i = blockIdx.x * blockDim.x + threadIdx.x;      // 0..32767
    (&g_inv[0][0])[i] = rsqrtf((&g_ssq[0][0])[i] + 1e-6f);
}

// ---------------------------------------------------------------------------
// Kernel 2: SINGLE-TERM fp16 mma.sync GEMM (ah*bh only).  CTA tile 128x128,
// K-chunk 32, 8 warps of 64x32, FOUR-stage cp.async (wait_group 2), one
// __syncthreads per chunk.  Buffer (16KB): Ah 8K | Bh 8K.
// ---------------------------------------------------------------------------
#define SMEM_DYN (4 * 16384)

template<int MODE>
__global__ void __launch_bounds__(256, 2)
gemm_hmma_kernel()
{
    constexpr int C   = MODE ? 2048 : 1024;
    constexpr int NCH = C / 32;
    constexpr int TI  = MODE ? 3 : 1;
    constexpr int SI  = MODE ? 2 : 0;

    extern __shared__ __align__(16) char sm[];

    const int tid  = threadIdx.x;
    const int lane = tid & 31;
    const int wid  = tid >> 5;
    const int wj   = wid >> 2;
    const int wi   = wid & 3;
    const int b  = blockIdx.z;
    const int i0 = blockIdx.x * 128;
    const int j0 = blockIdx.y * 128;

    const __half* Ahp = MODE ? g_h4t[0] : g_h3t[0];
    const __half* Bhp = MODE ? g_h4s[0] : g_h3s[0];

    const uint32_t sb0 = su32(sm);

    const int xa = tid >> 1, cp0 = (tid & 1) * 2;
    const uint32_t swz = (uint32_t)((xa >> 1) & 3);
    const size_t rowA = ((size_t)b * HW + j0 + xa) * C;
    const size_t rowB = ((size_t)b * HW + i0 + xa) * C;

    uint32_t aoff[4], aSw[4];
#pragma unroll
    for (int mi = 0; mi < 4; ++mi) {
        int r = wj * 64 + mi * 16 + (lane & 15);
        aoff[mi] = (uint32_t)(r * 64);
        aSw[mi]  = (uint32_t)((r >> 1) & 3);
    }
    const uint32_t hi16 = (uint32_t)((lane >> 4) & 1);
    uint32_t boff4[2], bSw4[2];
#pragma unroll
    for (int np = 0; np < 2; ++np) {
        int r = wi * 32 + (2 * np + ((lane >> 4) & 1)) * 8 + (lane & 7);
        boff4[np] = (uint32_t)(r * 64);
        bSw4[np]  = (uint32_t)((r >> 1) & 3);
    }
    const uint32_t khB = (uint32_t)((lane >> 3) & 1);

    float acc[4][4][4];
#pragma unroll
    for (int mi = 0; mi < 4; ++mi)
#pragma unroll
        for (int ni = 0; ni < 4; ++ni)
#pragma unroll
            for (int e = 0; e < 4; ++e) acc[mi][ni][e] = 0.f;

    auto issue = [&](int t, int buf) {
        const uint32_t db = sb0 + (uint32_t)buf * 16384u;
        const size_t k = (size_t)t * 32;
#pragma unroll
        for (int c = cp0; c < cp0 + 2; ++c) {
            uint32_t doff = (uint32_t)(xa * 64) + ((((uint32_t)c ^ swz) & 3u) << 4);
            cpasync16(db + doff,          Ahp + rowA + k + c * 8);
            cpasync16(db + 8192u + doff,  Bhp + rowB + k + c * 8);
        }
        cp_commit();
    };

    issue(0, 0);
    issue(1, 1);
    issue(2, 2);

    int bcur = 0;
    for (int t = 0; t < NCH; ++t) {
        if      (t + 2 < NCH) cp_wait2();
        else if (t + 1 < NCH) cp_wait1();
        else                  cp_wait0();
        __syncthreads();
        if (t + 3 < NCH) issue(t + 3, (bcur + 3) & 3);

        const uint32_t sb = sb0 + (uint32_t)bcur * 16384u;
#pragma unroll
        for (int ks = 0; ks < 2; ++ks) {
            uint32_t ah[4][4];
#pragma unroll
            for (int mi = 0; mi < 4; ++mi)
                ldmx4(ah[mi], sb + aoff[mi] + ((((uint32_t)(2 * ks) + hi16) ^ aSw[mi]) << 4));
#pragma unroll
            for (int np = 0; np < 2; ++np) {
                uint32_t bq[4];
                ldmx4(bq, sb + 8192u + boff4[np] + ((((uint32_t)(2 * ks) + khB) ^ bSw4[np]) << 4));
#pragma unroll
                for (int sub = 0; sub < 2; ++sub)
#pragma unroll
                    for (int mi = 0; mi < 4; ++mi)
                        mma16816(acc[mi][np * 2 + sub], ah[mi], &bq[2 * sub]);
            }
        }
        bcur = (bcur + 1) & 3;
    }

    // ---- epilogue (R12-proven) ----
    const float* invT = g_inv[TI] + (size_t)b * HW;
    const float* invS = g_inv[SI] + (size_t)b * HW;
    const int gid = lane >> 2, tig = lane & 3;
    const int jb = j0 + wj * 64 + gid;
    const int ib = i0 + wi * 32 + tig * 2;

    float tS[4][2];
#pragma unroll
    for (int mi = 0; mi < 4; ++mi) {
        tS[mi][0] = __ldg(invT + jb + mi * 16);
        tS[mi][1] = __ldg(invT + jb + mi * 16 + 8);
    }
    float2 sS[4];
#pragma unroll
    for (int ni = 0; ni < 4; ++ni)
        sS[ni] = *reinterpret_cast<const float2*>(invS + ib + ni * 8);

#pragma unroll
    for (int mi = 0; mi < 4; ++mi) {
        const int j = jb + mi * 16;
        const size_t row0 = ((size_t)b * HW + j) * HW;
        const size_t row8 = row0 + (size_t)8 * HW;
#pragma unroll
        for (int ni = 0; ni < 4; ++ni) {
            const int i = ib + ni * 8;
            float c0 = fmaxf(acc[mi][ni][0] * tS[mi][0] * sS[ni].x, 0.f);
            float c1 = fmaxf(acc[mi][ni][1] * tS[mi][0] * sS[ni].y, 0.f);
            float c2 = fmaxf(acc[mi][ni][2] * tS[mi][1] * sS[ni].x, 0.f);
            float c3 = fmaxf(acc[mi][ni][3] * tS[mi][1] * sS[ni].y, 0.f);
            if (MODE == 0) {
                *reinterpret_cast<float2*>(&g_M[row0 + i]) = make_float2(c0, c1);
                *reinterpret_cast<float2*>(&g_M[row8 + i]) = make_float2(c2, c3);
            } else {
                float2 o0 = *reinterpret_cast<const float2*>(&g_M[row0 + i]);
                float2 o8 = *reinterpret_cast<const float2*>(&g_M[row8 + i]);
                float m0 = o0.x * c0, m1 = o0.y * c1;
                float m2 = o8.x * c2, m3 = o8.y * c3;
                *reinterpret_cast<float2*>(&g_M[row0 + i]) = make_float2(m0, m1);
                *reinterpret_cast<float2*>(&g_M[row8 + i]) = make_float2(m2, m3);
                const size_t tc0 = ((size_t)b * HW + i) * HW;
                g_MT[tc0 + j]          = m0;
                g_MT[tc0 + HW + j]     = m1;
                g_MT[tc0 + j + 8]      = m2;
                g_MT[tc0 + HW + j + 8] = m3;
            }
        }
    }
}

// ---------------------------------------------------------------------------
// Exact dot of two feature columns from the hi+lo fp16 planes (error ~2^-22).
// ---------------------------------------------------------------------------
__device__ __forceinline__ float warp_dot(const __half* __restrict__ Th,
                                          const __half* __restrict__ Tl,
                                          const __half* __restrict__ Sh,
                                          const __half* __restrict__ Sl,
                                          size_t rt, size_t rs, int C, int lane)
{
    const __half2* ah = reinterpret_cast<const __half2*>(Th + rt);
    const __half2* al = reinterpret_cast<const __half2*>(Tl + rt);
    const __half2* bh = reinterpret_cast<const __half2*>(Sh + rs);
    const __half2* bl = reinterpret_cast<const __half2*>(Sl + rs);
    float acc = 0.f;
    for (int c = lane; c < C / 2; c += 32) {
        float2 a0 = __half22float2(ah[c]);
        float2 a1 = __half22float2(al[c]);
        float2 b0 = __half22float2(bh[c]);
        float2 b1 = __half22float2(bl[c]);
        acc = fmaf(a0.x + a1.x, b0.x + b1.x, acc);
        acc = fmaf(a0.y + a1.y, b0.y + b1.y, acc);
    }
    for (int o = 16; o; o >>= 1) acc += __shfl_down_sync(0xffffffffu, acc, o);
    return acc;
}

// ---------------------------------------------------------------------------
// Kernel 3: soft-argmax per column + EXACT argmax refinement.
// float4 loads; element mapping j = s*1024 + tid*4 + e  (float4 idx s*256+tid).
// ---------------------------------------------------------------------------
__global__ void __launch_bounds__(256)
softargmax_kernel(float* __restrict__ out)
{
    __shared__ float gtab[64];
    __shared__ float redf[8];
    __shared__ int   redi[8];
    __shared__ float bc[2];
    __shared__ float r3[3][8];
    __shared__ int   candj[32];
    __shared__ float candv[32];
    __shared__ int   candn;
    __shared__ float bestvS;

    const int pos = blockIdx.x;
    const int b   = blockIdx.y;
    const int dir = blockIdx.z;
    const int tid = threadIdx.x;
    const int lane = tid & 31, wid = tid >> 5;

    const float* row = (dir == 0 ? g_MT : g_M) + ((size_t)b * HW + pos) * HW;
    const float4* rowv = reinterpret_cast<const float4*>(row);

    if (tid < 64) gtab[tid] = expf(-(float)(tid * tid) * (1.0f / 50.0f));
    if (tid == 0) candn = 0;

    const int xq    = (tid * 4) & 63;    // x of element e=0
    const int ybase = tid >> 4;          // y within each s-slab

    // ---- pass 1: vector load + sum of squares
    float xr[16];
    float ss = 0.f;
#pragma unroll
    for (int s = 0; s < 4; ++s) {
        float4 v = rowv[s * 256 + tid];
        xr[s * 4 + 0] = v.x; xr[s * 4 + 1] = v.y;
        xr[s * 4 + 2] = v.z; xr[s * 4 + 3] = v.w;
        ss = fmaf(v.x, v.x, ss); ss = fmaf(v.y, v.y, ss);
        ss = fmaf(v.z, v.z, ss); ss = fmaf(v.w, v.w, ss);
    }
    for (int o = 16; o; o >>= 1) ss += __shfl_down_sync(0xffffffffu, ss, o);
    if (lane == 0) redf[wid] = ss;
    __syncthreads();
    if (wid == 0) {
        float v = (lane < 8) ? redf[lane] : 0.f;
        for (int o = 4; o; o >>= 1) v += __shfl_down_sync(0xffffffffu, v, o);
        if (lane == 0) bc[0] = rsqrtf(v + 1e-6f);
    }
    __syncthreads();
    const float invn = bc[0];

    // ---- pass 2: approx argmax (ascending j within thread)
    float bvv = -1.f; int bj = HW;
#pragma unroll
    for (int s = 0; s < 4; ++s)
#pragma unroll
        for (int e = 0; e < 4; ++e) {
            float x = xr[s * 4 + e];
            if (x > bvv) { bvv = x; bj = s * 1024 + tid * 4 + e; }
        }
    for (int o = 16; o; o >>= 1) {
        float ov = __shfl_down_sync(0xffffffffu, bvv, o);
        int   oj = __shfl_down_sync(0xffffffffu, bj,  o);
        if (ov > bvv || (ov == bvv && oj < bj)) { bvv = ov; bj = oj; }
    }
    __syncthreads();
    if (lane == 0) { redf[wid] = bvv; redi[wid] = bj; }
    __syncthreads();
    if (tid == 0) {
        float bestv = redf[0]; int bestj = redi[0];
        for (int q = 1; q < 8; ++q)
            if (redf[q] > bestv || (redf[q] == bestv && redi[q] < bestj)) {
                bestv = redf[q]; bestj = redi[q];
            }
        redi[0] = bestj;
        bestvS  = bestv;
    }
    __syncthreads();

    // ---- exact argmax refinement ----
    {
        const float thr = bestvS - 1e-3f / invn;
#pragma unroll
        for (int s = 0; s < 4; ++s)
#pragma unroll
            for (int e = 0; e < 4; ++e)
                if (xr[s * 4 + e] >= thr) {
                    int k = atomicAdd(&candn, 1);
                    if (k < 32) candj[k] = s * 1024 + tid * 4 + e;
                }
        __syncthreads();
        const int nc = candn;
        if (nc > 1 && nc <= 32) {
            for (int c = wid; c < nc; c += 8) {
                int jc = candj[c];
                int jt = (dir == 0) ? jc : pos;
                int js = (dir == 0) ? pos : jc;
                size_t rt3 = ((size_t)b * HW + jt) * 1024;
                size_t rs3 = ((size_t)b * HW + js) * 1024;
                size_t rt4 = ((size_t)b * HW + jt) * 2048;
                size_t rs4 = ((size_t)b * HW + js) * 2048;
                float d3 = warp_dot(g_h3t[0], g_h3t[1], g_h3s[0], g_h3s[1], rt3, rs3, 1024, lane);
                float d4 = warp_dot(g_h4t[0], g_h4t[1], g_h4s[0], g_h4s[1], rt4, rs4, 2048, lane);
                if (lane == 0) {
                    float c3 = d3 * g_inv[1][b * HW + jt] * g_inv[0][b * HW + js];
                    float c4 = d4 * g_inv[3][b * HW + jt] * g_inv[2][b * HW + js];
                    candv[c] = fmaxf(c3, 0.f) * fmaxf(c4, 0.f);
                }
            }
            __syncthreads();
            if (tid == 0) {
                float bv = -1.f; int bjx = HW;
                for (int c = 0; c < nc; ++c)
                    if (candv[c] > bv || (candv[c] == bv && candj[c] < bjx)) {
                        bv = candv[c]; bjx = candj[c];
                    }
                redi[0] = bjx;
            }
            __syncthreads();
        }
    }
    const int amax = redi[0];
    const int ax = amax & 63, ay = amax >> 6;

    // ---- pass 3: gaussian mask (per-e x lookup, per-s y lookup)
    float gxe[4];
#pragma unroll
    for (int e = 0; e < 4; ++e) {
        int dx = xq + e - ax; dx = dx < 0 ? -dx : dx;
        gxe[e] = gtab[dx];
    }
    float cm = -1.f;
#pragma unroll
    for (int s = 0; s < 4; ++s) {
        int dy = ybase + s * 16 - ay; dy = dy < 0 ? -dy : dy;
        float gy = gtab[dy];
#pragma unroll
        for (int e = 0; e < 4; ++e) {
            float g = gy * gxe[e];
            float c = (g < 1e-6f) ? -1.f : g * xr[s * 4 + e] * invn;
            xr[s * 4 + e] = c;
            cm = fmaxf(cm, c);
        }
    }
    for (int o = 16; o; o >>= 1) cm = fmaxf(cm, __shfl_down_sync(0xffffffffu, cm, o));
    __syncthreads();
    if (lane == 0) redf[wid] = cm;
    __syncthreads();
    if (wid == 0) {
        float v = (lane < 8) ? redf[lane] : -1.f;
        for (int o = 4; o; o >>= 1) v = fmaxf(v, __shfl_down_sync(0xffffffffu, v, o));
        if (lane == 0) bc[1] = v;
    }
    __syncthreads();
    const float m  = bc[1];
    const float e0 = __expf(-50.f * m);

    // ---- pass 4: stable softmax + soft-argmax sums
    float se = 0.f, sy = 0.f, sxe[4] = {0.f, 0.f, 0.f, 0.f};
#pragma unroll
    for (int s = 0; s < 4; ++s) {
        float yn = fmaf((float)(ybase + s * 16), 2.f / 63.f, -1.f);
#pragma unroll
        for (int e = 0; e < 4; ++e) {
            float c = xr[s * 4 + e];
            if (c >= 0.f) {
                float ex = __expf(50.f * (c - m)) - e0;
                se += ex;
                sy = fmaf(ex, yn, sy);
                sxe[e] += ex;
            }
        }
    }
    float sx = 0.f;
#pragma unroll
    for (int e = 0; e < 4; ++e)
        sx = fmaf(sxe[e], fmaf((float)(xq + e), 2.f / 63.f, -1.f), sx);

    for (int o = 16; o; o >>= 1) {
        se += __shfl_down_sync(0xffffffffu, se, o);
        sx += __shfl_down_sync(0xffffffffu, sx, o);
        sy += __shfl_down_sync(0xffffffffu, sy, o);
    }
    if (lane == 0) { r3[0][wid] = se; r3[1][wid] = sx; r3[2][wid] = sy; }
    __syncthreads();
    if (tid == 0) {
        float tse = 0.f, tsx = 0.f, tsy = 0.f;
        for (int q = 0; q < 8; ++q) { tse += r3[0][q]; tsx += r3[1][q]; tsy += r3[2][q]; }
        float denom = tse + 4096.f * e0;
        float gxo = tsx / denom;
        float gyo = tsy / denom;
        size_t ob = (size_t)dir * 32768 + (((size_t)b * 64 + (pos >> 6)) * 64 + (pos & 63)) * 2;
        out[ob]     = gxo;
        out[ob + 1] = gyo;
    }
}

// ---------------------------------------------------------------------------
extern "C" void kernel_launch(void* const* d_in, const int* in_sizes, int n_in,
                              void* d_out, int out_size)
{
    const float* s3 = (const float*)d_in[0];
    const float* t3 = (const float*)d_in[1];
    const float* s4 = (const float*)d_in[2];
    const float* t4 = (const float*)d_in[3];
    float* out = (float*)d_out;

    cudaFuncSetAttribute(gemm_hmma_kernel<0>, cudaFuncAttributeMaxDynamicSharedMemorySize, SMEM_DYN);
    cudaFuncSetAttribute(gemm_hmma_kernel<1>, cudaFuncAttributeMaxDynamicSharedMemorySize, SMEM_DYN);

    prep_kernel<<<256, 256>>>(out);
    split_kernel<<<dim3(64, 16, NB), 256>>>(s3, 0, 1024);
    split_kernel<<<dim3(64, 16, NB), 256>>>(t3, 1, 1024);
    split_kernel<<<dim3(64, 32, NB), 256>>>(s4, 2, 2048);
    split_kernel<<<dim3(64, 32, NB), 256>>>(t4, 3, 2048);
    inv_kernel<<<128, 256>>>();
    gemm_hmma_kernel<0><<<dim3(32, 32, NB), 256, SMEM_DYN>>>();
    gemm_hmma_kernel<1><<<dim3(32, 32, NB), 256, SMEM_DYN>>>();
    softargmax_kernel<<<dim3(HW, NB, 2), 256>>>(out);
}